// round 2
// baseline (speedup 1.0000x reference)
#include <cuda_runtime.h>
#include <cuda_fp16.h>
#include <cstdint>
#include <math.h>

// ---------------------------------------------------------------------------
// Portable (non-sm_103a-gated) tensor-core path: mma.sync + ldmatrix only.
// ---------------------------------------------------------------------------

#define LDSM_X4(r0, r1, r2, r3, addr) \
    asm volatile("ldmatrix.sync.aligned.m8n8.x4.shared.b16 {%0,%1,%2,%3}, [%4];" \
                 : "=r"(r0), "=r"(r1), "=r"(r2), "=r"(r3) : "r"(addr))

#define LDSM_X2(r0, r1, addr) \
    asm volatile("ldmatrix.sync.aligned.m8n8.x2.shared.b16 {%0,%1}, [%2];" \
                 : "=r"(r0), "=r"(r1) : "r"(addr))

#define MMA16816(c, a, b) \
    asm volatile("mma.sync.aligned.m16n8k16.row.col.f32.f16.f16.f32 " \
                 "{%0,%1,%2,%3}, {%4,%5,%6,%7}, {%8,%9}, {%0,%1,%2,%3};" \
                 : "+f"((c)[0]), "+f"((c)[1]), "+f"((c)[2]), "+f"((c)[3]) \
                 : "r"((a)[0]), "r"((a)[1]), "r"((a)[2]), "r"((a)[3]), \
                   "r"((b)[0]), "r"((b)[1]))

namespace {

__device__ __forceinline__ uint32_t smem_u32(const void* p) {
    uint32_t a;
    asm("{ .reg .u64 t; cvta.to.shared.u64 t, %1; cvt.u32.u64 %0, t; }"
        : "=r"(a) : "l"(p));
    return a;
}

__device__ __forceinline__ uint32_t pack_f16x2(float lo, float hi) {
    // d.lo = cvt(lo), d.hi = cvt(hi)
    uint32_t r;
    asm("cvt.rn.f16x2.f32 %0, %1, %2;" : "=r"(r) : "f"(hi), "f"(lo));
    return r;
}

__device__ __forceinline__ float softplus_dev(float s) {
    return (s > 20.0f) ? s : log1pf(expf(s));
}

// SMEM strides: 72 halfs per row (144 B) -> ldmatrix bank-conflict free.
constexpr int WSTR = 72;
constexpr int NCTA = 2048;
constexpr int CTA_THREADS = 128;

__global__ void __launch_bounds__(128) ngp_mlp_kernel(
    const float* __restrict__ feat,
    const float* __restrict__ W0, const float* __restrict__ b0,
    const float* __restrict__ W1, const float* __restrict__ b1,
    const float* __restrict__ Ws, const float* __restrict__ bs,
    const float* __restrict__ Wr, const float* __restrict__ br,
    float* __restrict__ sigma_out, float* __restrict__ rgb_out,
    int rows_per_cta)
{
    // Weights transposed to [N][K] fp16 (row.col mma wants B col-major = B[n][k]).
    __shared__ __half w0t[64 * WSTR];   // [n<64][k<32]
    __shared__ __half w1t[64 * WSTR];   // [n<64][k<64]
    __shared__ __half w2t[24 * WSTR];   // [n<24][k<64]; n0=Ws, n1..16=Wr, 17..23=0
    __shared__ float  sbias[152];       // 0..63 b0 | 64..127 b1 | 128..151 head
    __shared__ __half act[4][16 * WSTR];  // per-warp activation staging

    const int tid  = threadIdx.x;
    const int wid  = tid >> 5;
    const int lane = tid & 31;

    // ---- stage weights (fp32 gmem [K][N] -> fp16 smem [N][K]) ----
    for (int i = tid; i < 32 * 64; i += CTA_THREADS) {
        int k = i >> 6, n = i & 63;
        w0t[n * WSTR + k] = __float2half(W0[i]);
    }
    for (int i = tid; i < 64 * 64; i += CTA_THREADS) {
        int k = i >> 6, n = i & 63;
        w1t[n * WSTR + k] = __float2half(W1[i]);
    }
    for (int i = tid; i < 24 * WSTR; i += CTA_THREADS)
        w2t[i] = __float2half(0.0f);
    if (tid < 64) { sbias[tid] = b0[tid]; sbias[64 + tid] = b1[tid]; }
    if (tid < 24)
        sbias[128 + tid] = (tid == 0) ? (bs[0] - 1.0f)
                         : (tid <= 16 ? br[tid - 1] : 0.0f);
    __syncthreads();
    if (tid < 64)
        w2t[0 * WSTR + tid] = __float2half(Ws[tid]);       // head col 0: sigma
    for (int i = tid; i < 64 * 16; i += CTA_THREADS) {      // head cols 1..16
        int k = i >> 4, n = i & 15;
        w2t[(n + 1) * WSTR + k] = __float2half(Wr[i]);
    }
    __syncthreads();

    // ---- load all B-fragments into registers once (reused every iter) ----
    const uint32_t w0b = smem_u32(w0t), w1b = smem_u32(w1t), w2b = smem_u32(w2t);
    const int l15  = lane & 15;
    const int brow = l15 & 7;
    const int bhal = (l15 >> 3) & 1;

    uint32_t bw0[2][8][2], bw1[4][8][2], bw2[4][3][2];
    #pragma unroll
    for (int kt = 0; kt < 2; kt++)
        #pragma unroll
        for (int nt = 0; nt < 8; nt++) {
            uint32_t ad = w0b + (nt * 8 + brow) * (WSTR * 2) + kt * 32 + bhal * 16;
            LDSM_X2(bw0[kt][nt][0], bw0[kt][nt][1], ad);
        }
    #pragma unroll
    for (int kt = 0; kt < 4; kt++)
        #pragma unroll
        for (int nt = 0; nt < 8; nt++) {
            uint32_t ad = w1b + (nt * 8 + brow) * (WSTR * 2) + kt * 32 + bhal * 16;
            LDSM_X2(bw1[kt][nt][0], bw1[kt][nt][1], ad);
        }
    #pragma unroll
    for (int kt = 0; kt < 4; kt++)
        #pragma unroll
        for (int nt = 0; nt < 3; nt++) {
            uint32_t ad = w2b + (nt * 8 + brow) * (WSTR * 2) + kt * 32 + bhal * 16;
            LDSM_X2(bw2[kt][nt][0], bw2[kt][nt][1], ad);
        }

    // ---- per-thread bias fragments (accumulator init; c2/c3 reuse c0/c1) ----
    const int col2 = (lane & 3) * 2;
    float bb0[8][2], bb1[8][2], bbh[3][2];
    #pragma unroll
    for (int nt = 0; nt < 8; nt++) {
        bb0[nt][0] = sbias[nt * 8 + col2];       bb0[nt][1] = sbias[nt * 8 + col2 + 1];
        bb1[nt][0] = sbias[64 + nt * 8 + col2];  bb1[nt][1] = sbias[64 + nt * 8 + col2 + 1];
    }
    #pragma unroll
    for (int nt = 0; nt < 3; nt++) {
        bbh[nt][0] = sbias[128 + nt * 8 + col2];
        bbh[nt][1] = sbias[128 + nt * 8 + col2 + 1];
    }

    // ---- per-warp constant addressing ----
    const uint32_t actw = smem_u32(&act[wid][0]);
    uint32_t a_addr[4];
    #pragma unroll
    for (int kt = 0; kt < 4; kt++)
        a_addr[kt] = actw + l15 * (WSTR * 2) + ((lane >> 4) & 1) * 16 + kt * 32;

    const int ld_c4  = lane & 7;        // float4 column within a row
    const int ld_r0  = lane >> 3;       // base row for q=0
    const int ep_row = lane >> 2;       // epilogue row (and +8)

    const int cta_base = blockIdx.x * rows_per_cta;
    const float4* fbase = (const float4*)feat + (size_t)(cta_base + wid * 16) * 8;

    for (int it = 0; it < rows_per_cta; it += 64) {
        const int r0 = cta_base + it + wid * 16;     // this warp's 16 rows
        const float4* fp = fbase + (size_t)it * 8;

        // -- load feat (coalesced), pack fp16, stage to act --
        float4 v[4];
        #pragma unroll
        for (int q = 0; q < 4; q++)
            v[q] = fp[(size_t)(ld_r0 + 4 * q) * 8 + ld_c4];
        __syncwarp();   // prior ldmatrix readers done before overwrite
        #pragma unroll
        for (int q = 0; q < 4; q++) {
            __half* dst = &act[wid][(ld_r0 + 4 * q) * WSTR + ld_c4 * 4];
            ((uint32_t*)dst)[0] = pack_f16x2(v[q].x, v[q].y);
            ((uint32_t*)dst)[1] = pack_f16x2(v[q].z, v[q].w);
        }
        __syncwarp();

        // -- layer 0: [16,32] @ W0 -> [16,64] --
        uint32_t A[4][4];
        LDSM_X4(A[0][0], A[0][1], A[0][2], A[0][3], a_addr[0]);
        LDSM_X4(A[1][0], A[1][1], A[1][2], A[1][3], a_addr[1]);
        float c[8][4];
        #pragma unroll
        for (int nt = 0; nt < 8; nt++) {
            c[nt][0] = bb0[nt][0]; c[nt][1] = bb0[nt][1];
            c[nt][2] = bb0[nt][0]; c[nt][3] = bb0[nt][1];
        }
        #pragma unroll
        for (int kt = 0; kt < 2; kt++)
            #pragma unroll
            for (int nt = 0; nt < 8; nt++)
                MMA16816(c[nt], A[kt], bw0[kt][nt]);

        // relu + pack -> act
        __syncwarp();   // ldmatrix A0 reads done before overwrite
        #pragma unroll
        for (int nt = 0; nt < 8; nt++) {
            uint32_t h01 = pack_f16x2(fmaxf(c[nt][0], 0.f), fmaxf(c[nt][1], 0.f));
            uint32_t h23 = pack_f16x2(fmaxf(c[nt][2], 0.f), fmaxf(c[nt][3], 0.f));
            *(uint32_t*)&act[wid][ep_row * WSTR + nt * 8 + col2]       = h01;
            *(uint32_t*)&act[wid][(ep_row + 8) * WSTR + nt * 8 + col2] = h23;
        }
        __syncwarp();

        // -- layer 1: [16,64] @ W1 -> [16,64] --
        #pragma unroll
        for (int kt = 0; kt < 4; kt++)
            LDSM_X4(A[kt][0], A[kt][1], A[kt][2], A[kt][3], a_addr[kt]);
        #pragma unroll
        for (int nt = 0; nt < 8; nt++) {
            c[nt][0] = bb1[nt][0]; c[nt][1] = bb1[nt][1];
            c[nt][2] = bb1[nt][0]; c[nt][3] = bb1[nt][1];
        }
        #pragma unroll
        for (int kt = 0; kt < 4; kt++)
            #pragma unroll
            for (int nt = 0; nt < 8; nt++)
                MMA16816(c[nt], A[kt], bw1[kt][nt]);

        __syncwarp();
        #pragma unroll
        for (int nt = 0; nt < 8; nt++) {
            uint32_t h01 = pack_f16x2(fmaxf(c[nt][0], 0.f), fmaxf(c[nt][1], 0.f));
            uint32_t h23 = pack_f16x2(fmaxf(c[nt][2], 0.f), fmaxf(c[nt][3], 0.f));
            *(uint32_t*)&act[wid][ep_row * WSTR + nt * 8 + col2]       = h01;
            *(uint32_t*)&act[wid][(ep_row + 8) * WSTR + nt * 8 + col2] = h23;
        }
        __syncwarp();

        // -- heads: [16,64] @ [Ws|Wr|0] -> [16,24] (col0 = sigma logit) --
        #pragma unroll
        for (int kt = 0; kt < 4; kt++)
            LDSM_X4(A[kt][0], A[kt][1], A[kt][2], A[kt][3], a_addr[kt]);
        float ch[3][4];
        #pragma unroll
        for (int nt = 0; nt < 3; nt++) {
            ch[nt][0] = bbh[nt][0]; ch[nt][1] = bbh[nt][1];
            ch[nt][2] = bbh[nt][0]; ch[nt][3] = bbh[nt][1];
        }
        #pragma unroll
        for (int kt = 0; kt < 4; kt++)
            #pragma unroll
            for (int nt = 0; nt < 3; nt++)
                MMA16816(ch[nt], A[kt], bw2[kt][nt]);

        // -- epilogue stores --
        const int gr0 = r0 + ep_row;
        const int gr1 = gr0 + 8;
        float* rg0 = rgb_out + (size_t)gr0 * 16;
        float* rg1 = rgb_out + (size_t)gr1 * 16;

        if (col2 == 0) {
            sigma_out[gr0] = softplus_dev(ch[0][0]);
            sigma_out[gr1] = softplus_dev(ch[0][2]);
            rg0[0]  = ch[0][1];  rg1[0]  = ch[0][3];
            rg0[15] = ch[2][0];  rg1[15] = ch[2][2];
        } else {
            rg0[col2 - 1] = ch[0][0];  rg0[col2] = ch[0][1];
            rg1[col2 - 1] = ch[0][2];  rg1[col2] = ch[0][3];
        }
        rg0[7 + col2] = ch[1][0];  rg0[8 + col2] = ch[1][1];
        rg1[7 + col2] = ch[1][2];  rg1[8 + col2] = ch[1][3];
    }
}

}  // namespace

extern "C" void kernel_launch(void* const* d_in, const int* in_sizes, int n_in,
                              void* d_out, int out_size) {
    const float* feat = (const float*)d_in[0];
    const float* W0   = (const float*)d_in[1];
    const float* b0   = (const float*)d_in[2];
    const float* W1   = (const float*)d_in[3];
    const float* b1   = (const float*)d_in[4];
    const float* Ws   = (const float*)d_in[5];
    const float* bs   = (const float*)d_in[6];
    const float* Wr   = (const float*)d_in[7];
    const float* br   = (const float*)d_in[8];

    float* out = (float*)d_out;
    const int Bn = in_sizes[0] / 32;           // rows (2^21)
    float* sigma = out;                         // [B]
    float* rgb   = out + Bn;                    // [B,16] row-major

    const int rpc = Bn / NCTA;                  // 1024 rows per CTA
    ngp_mlp_kernel<<<NCTA, CTA_THREADS>>>(feat, W0, b0, W1, b1, Ws, bs, Wr, br,
                                          sigma, rgb, rpc);
}

// round 5
// speedup vs baseline: 1.2201x; 1.2201x over previous
#include <cuda_runtime.h>
#include <cuda_fp16.h>
#include <cstdint>
#include <math.h>

// ---------------------------------------------------------------------------
// Portable tensor-core path: mma.sync + ldmatrix only (no sm_103a-gated PTX).
// Fully-fused MLP: inter-layer activations stay in registers via exact
// C-fragment -> A-fragment repacking (layouts coincide for m16n8k16).
// ---------------------------------------------------------------------------

#define LDSM_X4(r0, r1, r2, r3, addr) \
    asm volatile("ldmatrix.sync.aligned.m8n8.x4.shared.b16 {%0,%1,%2,%3}, [%4];" \
                 : "=r"(r0), "=r"(r1), "=r"(r2), "=r"(r3) : "r"(addr))

#define LDSM_X2(r0, r1, addr) \
    asm volatile("ldmatrix.sync.aligned.m8n8.x2.shared.b16 {%0,%1}, [%2];" \
                 : "=r"(r0), "=r"(r1) : "r"(addr))

#define MMA16816(c, a, b) \
    asm volatile("mma.sync.aligned.m16n8k16.row.col.f32.f16.f16.f32 " \
                 "{%0,%1,%2,%3}, {%4,%5,%6,%7}, {%8,%9}, {%0,%1,%2,%3};" \
                 : "+f"((c)[0]), "+f"((c)[1]), "+f"((c)[2]), "+f"((c)[3]) \
                 : "r"((a)[0]), "r"((a)[1]), "r"((a)[2]), "r"((a)[3]), \
                   "r"((b)[0]), "r"((b)[1]))

namespace {

__device__ __forceinline__ uint32_t smem_u32(const void* p) {
    uint32_t a;
    asm("{ .reg .u64 t; cvta.to.shared.u64 t, %1; cvt.u32.u64 %0, t; }"
        : "=r"(a) : "l"(p));
    return a;
}

__device__ __forceinline__ uint32_t pack_f16x2(float lo, float hi) {
    uint32_t r;
    asm("cvt.rn.f16x2.f32 %0, %1, %2;" : "=r"(r) : "f"(hi), "f"(lo));
    return r;
}

// relu both floats, pack to f16x2
__device__ __forceinline__ uint32_t relu_pack(float lo, float hi) {
    return pack_f16x2(fmaxf(lo, 0.0f), fmaxf(hi, 0.0f));
}

__device__ __forceinline__ float softplus_dev(float s) {
    return (s > 20.0f) ? s : log1pf(expf(s));
}

constexpr int WSTR = 72;     // halfs per SMEM row (144B) -> ldmatrix conflict-free
constexpr int NCTA = 2048;
constexpr int CTA_THREADS = 128;

__global__ void __launch_bounds__(128) ngp_mlp_kernel(
    const float* __restrict__ feat,
    const float* __restrict__ W0, const float* __restrict__ b0,
    const float* __restrict__ W1, const float* __restrict__ b1,
    const float* __restrict__ Ws, const float* __restrict__ bs,
    const float* __restrict__ Wr, const float* __restrict__ br,
    float* __restrict__ sigma_out, float* __restrict__ rgb_out,
    int rows_per_cta)
{
    __shared__ __half w0t[64 * WSTR];      // [n<64][k<32] fp16, transposed
    __shared__ __half w1t[64 * WSTR];      // [n<64][k<64]
    __shared__ __half w2t[24 * WSTR];      // [n<24][k<64]; n0=Ws, n1..16=Wr
    __shared__ float  sbias[152];          // b0 | b1 | head(bs-1, br, 0)
    __shared__ __half act[4][16 * WSTR];   // per-warp INPUT staging only

    const int tid  = threadIdx.x;
    const int wid  = tid >> 5;
    const int lane = tid & 31;

    // ---- stage weights: fp32 gmem [K][N] -> fp16 smem [N][K] ----
    for (int i = tid; i < 32 * 64; i += CTA_THREADS) {
        int k = i >> 6, n = i & 63;
        w0t[n * WSTR + k] = __float2half(W0[i]);
    }
    for (int i = tid; i < 64 * 64; i += CTA_THREADS) {
        int k = i >> 6, n = i & 63;
        w1t[n * WSTR + k] = __float2half(W1[i]);
    }
    for (int i = tid; i < 24 * WSTR; i += CTA_THREADS)
        w2t[i] = __float2half(0.0f);
    if (tid < 64) { sbias[tid] = b0[tid]; sbias[64 + tid] = b1[tid]; }
    if (tid < 24)
        sbias[128 + tid] = (tid == 0) ? (bs[0] - 1.0f)
                         : (tid <= 16 ? br[tid - 1] : 0.0f);
    __syncthreads();
    if (tid < 64)
        w2t[0 * WSTR + tid] = __float2half(Ws[tid]);        // col 0: sigma
    for (int i = tid; i < 64 * 16; i += CTA_THREADS) {       // cols 1..16: rgb
        int k = i >> 4, n = i & 15;
        w2t[(n + 1) * WSTR + k] = __float2half(Wr[i]);
    }
    __syncthreads();

    // ---- B fragments to registers once (reused by all iterations) ----
    const uint32_t w0b = smem_u32(w0t), w1b = smem_u32(w1t), w2b = smem_u32(w2t);
    const int l15  = lane & 15;
    const int brow = l15 & 7;
    const int bhal = (l15 >> 3) & 1;

    uint32_t bw0[2][8][2], bw1[4][8][2], bw2[4][3][2];
    #pragma unroll
    for (int kt = 0; kt < 2; kt++)
        #pragma unroll
        for (int nt = 0; nt < 8; nt++) {
            uint32_t ad = w0b + (nt * 8 + brow) * (WSTR * 2) + kt * 32 + bhal * 16;
            LDSM_X2(bw0[kt][nt][0], bw0[kt][nt][1], ad);
        }
    #pragma unroll
    for (int kt = 0; kt < 4; kt++)
        #pragma unroll
        for (int nt = 0; nt < 8; nt++) {
            uint32_t ad = w1b + (nt * 8 + brow) * (WSTR * 2) + kt * 32 + bhal * 16;
            LDSM_X2(bw1[kt][nt][0], bw1[kt][nt][1], ad);
        }
    #pragma unroll
    for (int kt = 0; kt < 4; kt++)
        #pragma unroll
        for (int nt = 0; nt < 3; nt++) {
            uint32_t ad = w2b + (nt * 8 + brow) * (WSTR * 2) + kt * 32 + bhal * 16;
            LDSM_X2(bw2[kt][nt][0], bw2[kt][nt][1], ad);
        }

    // ---- per-thread bias fragments (accumulator init) ----
    const int col2 = (lane & 3) * 2;
    float bb0[8][2], bb1[8][2], bbh[3][2];
    #pragma unroll
    for (int nt = 0; nt < 8; nt++) {
        bb0[nt][0] = sbias[nt * 8 + col2];       bb0[nt][1] = sbias[nt * 8 + col2 + 1];
        bb1[nt][0] = sbias[64 + nt * 8 + col2];  bb1[nt][1] = sbias[64 + nt * 8 + col2 + 1];
    }
    #pragma unroll
    for (int nt = 0; nt < 3; nt++) {
        bbh[nt][0] = sbias[128 + nt * 8 + col2];
        bbh[nt][1] = sbias[128 + nt * 8 + col2 + 1];
    }

    // ---- addressing ----
    const uint32_t actw = smem_u32(&act[wid][0]);
    uint32_t a_addr[2];
    #pragma unroll
    for (int kt = 0; kt < 2; kt++)
        a_addr[kt] = actw + l15 * (WSTR * 2) + ((lane >> 4) & 1) * 16 + kt * 32;

    const int ld_c4  = lane & 7;
    const int ld_r0  = lane >> 3;
    const int ep_row = lane >> 2;

    const int cta_base = blockIdx.x * rows_per_cta;
    const float4* fbase = (const float4*)feat + (size_t)(cta_base + wid * 16) * 8;

    // prime the pipeline: load iteration 0's feat
    float4 v[4];
    #pragma unroll
    for (int q = 0; q < 4; q++)
        v[q] = fbase[(size_t)(ld_r0 + 4 * q) * 8 + ld_c4];

    #pragma unroll 1
    for (int it = 0; it < rows_per_cta; it += 64) {
        const int r0 = cta_base + it + wid * 16;

        // -- stage current feat to SMEM (fp16) --
        __syncwarp();
        #pragma unroll
        for (int q = 0; q < 4; q++) {
            __half* dst = &act[wid][(ld_r0 + 4 * q) * WSTR + ld_c4 * 4];
            ((uint32_t*)dst)[0] = pack_f16x2(v[q].x, v[q].y);
            ((uint32_t*)dst)[1] = pack_f16x2(v[q].z, v[q].w);
        }
        __syncwarp();

        // -- layer-0 A fragments --
        uint32_t A[4][4];
        LDSM_X4(A[0][0], A[0][1], A[0][2], A[0][3], a_addr[0]);
        LDSM_X4(A[1][0], A[1][1], A[1][2], A[1][3], a_addr[1]);

        // -- prefetch next iteration's feat (overlaps all MMAs below) --
        {
            const int itn = (it + 64 < rows_per_cta) ? it + 64 : it;
            const float4* fpn = fbase + (size_t)itn * 8;
            #pragma unroll
            for (int q = 0; q < 4; q++)
                v[q] = fpn[(size_t)(ld_r0 + 4 * q) * 8 + ld_c4];
        }

        // -- layer 0: [16,32] @ W0 -> c[8][4] --
        float c[8][4];
        #pragma unroll
        for (int nt = 0; nt < 8; nt++) {
            c[nt][0] = bb0[nt][0]; c[nt][1] = bb0[nt][1];
            c[nt][2] = bb0[nt][0]; c[nt][3] = bb0[nt][1];
        }
        #pragma unroll
        for (int kt = 0; kt < 2; kt++)
            #pragma unroll
            for (int nt = 0; nt < 8; nt++)
                MMA16816(c[nt], A[kt], bw0[kt][nt]);

        // -- repack C -> A (relu fused, registers only) --
        #pragma unroll
        for (int kt = 0; kt < 4; kt++) {
            A[kt][0] = relu_pack(c[2 * kt][0],     c[2 * kt][1]);
            A[kt][1] = relu_pack(c[2 * kt][2],     c[2 * kt][3]);
            A[kt][2] = relu_pack(c[2 * kt + 1][0], c[2 * kt + 1][1]);
            A[kt][3] = relu_pack(c[2 * kt + 1][2], c[2 * kt + 1][3]);
        }

        // -- layer 1: [16,64] @ W1 --
        #pragma unroll
        for (int nt = 0; nt < 8; nt++) {
            c[nt][0] = bb1[nt][0]; c[nt][1] = bb1[nt][1];
            c[nt][2] = bb1[nt][0]; c[nt][3] = bb1[nt][1];
        }
        #pragma unroll
        for (int kt = 0; kt < 4; kt++)
            #pragma unroll
            for (int nt = 0; nt < 8; nt++)
                MMA16816(c[nt], A[kt], bw1[kt][nt]);

        // -- repack again --
        #pragma unroll
        for (int kt = 0; kt < 4; kt++) {
            A[kt][0] = relu_pack(c[2 * kt][0],     c[2 * kt][1]);
            A[kt][1] = relu_pack(c[2 * kt][2],     c[2 * kt][3]);
            A[kt][2] = relu_pack(c[2 * kt + 1][0], c[2 * kt + 1][1]);
            A[kt][3] = relu_pack(c[2 * kt + 1][2], c[2 * kt + 1][3]);
        }

        // -- heads: [16,64] @ [Ws|Wr|0] -> [16,24] --
        float ch[3][4];
        #pragma unroll
        for (int nt = 0; nt < 3; nt++) {
            ch[nt][0] = bbh[nt][0]; ch[nt][1] = bbh[nt][1];
            ch[nt][2] = bbh[nt][0]; ch[nt][3] = bbh[nt][1];
        }
        #pragma unroll
        for (int kt = 0; kt < 4; kt++)
            #pragma unroll
            for (int nt = 0; nt < 3; nt++)
                MMA16816(ch[nt], A[kt], bw2[kt][nt]);

        // -- epilogue stores --
        const int gr0 = r0 + ep_row;
        const int gr1 = gr0 + 8;
        float* rg0 = rgb_out + (size_t)gr0 * 16;
        float* rg1 = rgb_out + (size_t)gr1 * 16;

        if (col2 == 0) {
            sigma_out[gr0] = softplus_dev(ch[0][0]);
            sigma_out[gr1] = softplus_dev(ch[0][2]);
            rg0[0]  = ch[0][1];  rg1[0]  = ch[0][3];
            rg0[15] = ch[2][0];  rg1[15] = ch[2][2];
        } else {
            rg0[col2 - 1] = ch[0][0];  rg0[col2] = ch[0][1];
            rg1[col2 - 1] = ch[0][2];  rg1[col2] = ch[0][3];
        }
        rg0[7 + col2] = ch[1][0];  rg0[8 + col2] = ch[1][1];
        rg1[7 + col2] = ch[1][2];  rg1[8 + col2] = ch[1][3];
    }
}

}  // namespace

extern "C" void kernel_launch(void* const* d_in, const int* in_sizes, int n_in,
                              void* d_out, int out_size) {
    const float* feat = (const float*)d_in[0];
    const float* W0   = (const float*)d_in[1];
    const float* b0   = (const float*)d_in[2];
    const float* W1   = (const float*)d_in[3];
    const float* b1   = (const float*)d_in[4];
    const float* Ws   = (const float*)d_in[5];
    const float* bs   = (const float*)d_in[6];
    const float* Wr   = (const float*)d_in[7];
    const float* br   = (const float*)d_in[8];

    float* out = (float*)d_out;
    const int Bn = in_sizes[0] / 32;           // rows (2^21)
    float* sigma = out;                         // [B]
    float* rgb   = out + Bn;                    // [B,16]

    const int rpc = Bn / NCTA;                  // 1024
    ngp_mlp_kernel<<<NCTA, CTA_THREADS>>>(feat, W0, b0, W1, b1, Ws, bs, Wr, br,
                                          sigma, rgb, rpc);
}

// round 6
// speedup vs baseline: 1.3815x; 1.1323x over previous
#include <cuda_runtime.h>
#include <cuda_fp16.h>
#include <cstdint>
#include <math.h>

// ---------------------------------------------------------------------------
// Portable tensor-core path: mma.sync + ldmatrix (no sm_103a-gated PTX).
// Round 6: occupancy-focused. Weights streamed from SMEM per iteration
// (transient regs) instead of 120 persistent regs/thread; bias init via
// non-hoistable LDS. Forced 4 CTAs/SM.
// ---------------------------------------------------------------------------

#define LDSM_X4(r0, r1, r2, r3, addr) \
    asm volatile("ldmatrix.sync.aligned.m8n8.x4.shared.b16 {%0,%1,%2,%3}, [%4];" \
                 : "=r"(r0), "=r"(r1), "=r"(r2), "=r"(r3) : "r"(addr))

#define LDSM_X2(r0, r1, addr) \
    asm volatile("ldmatrix.sync.aligned.m8n8.x2.shared.b16 {%0,%1}, [%2];" \
                 : "=r"(r0), "=r"(r1) : "r"(addr))

#define MMA16816(c, a0, a1, a2, a3, b0, b1) \
    asm volatile("mma.sync.aligned.m16n8k16.row.col.f32.f16.f16.f32 " \
                 "{%0,%1,%2,%3}, {%4,%5,%6,%7}, {%8,%9}, {%0,%1,%2,%3};" \
                 : "+f"((c)[0]), "+f"((c)[1]), "+f"((c)[2]), "+f"((c)[3]) \
                 : "r"(a0), "r"(a1), "r"(a2), "r"(a3), "r"(b0), "r"(b1))

namespace {

__device__ __forceinline__ uint32_t smem_u32(const void* p) {
    uint32_t a;
    asm("{ .reg .u64 t; cvta.to.shared.u64 t, %1; cvt.u32.u64 %0, t; }"
        : "=r"(a) : "l"(p));
    return a;
}

__device__ __forceinline__ uint32_t pack_f16x2(float lo, float hi) {
    uint32_t r;
    asm("cvt.rn.f16x2.f32 %0, %1, %2;" : "=r"(r) : "f"(hi), "f"(lo));
    return r;
}

// pack two floats to f16x2 then relu both halves in one max.f16x2
__device__ __forceinline__ uint32_t pack_relu2(float lo, float hi) {
    uint32_t r = pack_f16x2(lo, hi);
    asm("max.f16x2 %0, %0, %1;" : "+r"(r) : "r"(0u));
    return r;
}

// non-hoistable bias load (keeps values out of persistent registers)
__device__ __forceinline__ float2 lds64(uint32_t addr) {
    float2 r;
    asm volatile("ld.shared.v2.f32 {%0,%1}, [%2];"
                 : "=f"(r.x), "=f"(r.y) : "r"(addr));
    return r;
}

__device__ __forceinline__ float softplus_dev(float s) {
    return (s > 20.0f) ? s : log1pf(expf(s));
}

constexpr int WSTR = 72;     // halfs per SMEM row (144B) -> ldmatrix conflict-free
constexpr int NCTA = 2048;
constexpr int CTA_THREADS = 128;

__global__ void __launch_bounds__(128, 4) ngp_mlp_kernel(
    const float* __restrict__ feat,
    const float* __restrict__ W0, const float* __restrict__ b0,
    const float* __restrict__ W1, const float* __restrict__ b1,
    const float* __restrict__ Ws, const float* __restrict__ bs,
    const float* __restrict__ Wr, const float* __restrict__ br,
    float* __restrict__ sigma_out, float* __restrict__ rgb_out,
    int rows_per_cta)
{
    __shared__ __half w0t[64 * WSTR];      // [n<64][k<32] fp16, transposed
    __shared__ __half w1t[64 * WSTR];      // [n<64][k<64]
    __shared__ __half w2t[24 * WSTR];      // [n<24][k<64]; n0=Ws, n1..16=Wr
    __shared__ float  sbias[152];          // b0 | b1 | head(bs-1, br, 0)
    __shared__ __half act[4][16 * WSTR];   // per-warp input staging

    const int tid  = threadIdx.x;
    const int wid  = tid >> 5;
    const int lane = tid & 31;

    // ---- stage weights: fp32 gmem [K][N] -> fp16 smem [N][K] ----
    for (int i = tid; i < 32 * 64; i += CTA_THREADS) {
        int k = i >> 6, n = i & 63;
        w0t[n * WSTR + k] = __float2half(W0[i]);
    }
    for (int i = tid; i < 64 * 64; i += CTA_THREADS) {
        int k = i >> 6, n = i & 63;
        w1t[n * WSTR + k] = __float2half(W1[i]);
    }
    for (int i = tid; i < 24 * WSTR; i += CTA_THREADS)
        w2t[i] = __float2half(0.0f);
    if (tid < 64) { sbias[tid] = b0[tid]; sbias[64 + tid] = b1[tid]; }
    if (tid < 24)
        sbias[128 + tid] = (tid == 0) ? (bs[0] - 1.0f)
                         : (tid <= 16 ? br[tid - 1] : 0.0f);
    __syncthreads();
    if (tid < 64)
        w2t[0 * WSTR + tid] = __float2half(Ws[tid]);        // col 0: sigma
    for (int i = tid; i < 64 * 16; i += CTA_THREADS) {       // cols 1..16: rgb
        int k = i >> 4, n = i & 15;
        w2t[(n + 1) * WSTR + k] = __float2half(Wr[i]);
    }
    __syncthreads();

    // ---- addressing ----
    const uint32_t w0b = smem_u32(w0t), w1b = smem_u32(w1t), w2b = smem_u32(w2t);
    const uint32_t sb  = smem_u32(sbias);
    const int l15  = lane & 15;
    const int col2 = (lane & 3) * 2;

    // B-fragment ldmatrix lane terms
    //  X4 (two n-tiles): lanes 0-15 tile np (k-halves), 16-31 tile np+1
    const uint32_t bl4 = (uint32_t)((((lane >> 4) & 1) * 8 + (lane & 7)) * (WSTR * 2)
                                    + ((lane >> 3) & 1) * 16);
    //  X2 (one n-tile): lanes 0-15
    const uint32_t bl2 = (uint32_t)((l15 & 7) * (WSTR * 2) + ((l15 >> 3) & 1) * 16);

    // activation ldmatrix addresses
    const uint32_t actw = smem_u32(&act[wid][0]);
    const uint32_t a_addr0 = actw + l15 * (WSTR * 2) + ((lane >> 4) & 1) * 16;
    const uint32_t a_addr1 = a_addr0 + 32;

    const int ld_c4  = lane & 7;
    const int ld_r0  = lane >> 3;
    const int ep_row = lane >> 2;

    // bias base addresses (bytes)
    const uint32_t sb0 = sb + (uint32_t)col2 * 4;        // b0
    const uint32_t sb1 = sb0 + 256;                      // b1
    const uint32_t sbh = sb0 + 512;                      // head

    const int cta_base = blockIdx.x * rows_per_cta;
    const float4* fbase = (const float4*)feat + (size_t)(cta_base + wid * 16) * 8;

    // prime pipeline
    float4 v[4];
    #pragma unroll
    for (int q = 0; q < 4; q++)
        v[q] = fbase[(size_t)(ld_r0 + 4 * q) * 8 + ld_c4];

    #pragma unroll 1
    for (int it = 0; it < rows_per_cta; it += 64) {
        const int r0 = cta_base + it + wid * 16;

        // -- stage current feat to SMEM (fp16) --
        __syncwarp();
        #pragma unroll
        for (int q = 0; q < 4; q++) {
            __half* dst = &act[wid][(ld_r0 + 4 * q) * WSTR + ld_c4 * 4];
            ((uint32_t*)dst)[0] = pack_f16x2(v[q].x, v[q].y);
            ((uint32_t*)dst)[1] = pack_f16x2(v[q].z, v[q].w);
        }
        __syncwarp();

        // -- layer-0 A fragments --
        uint32_t A[4][4];
        LDSM_X4(A[0][0], A[0][1], A[0][2], A[0][3], a_addr0);
        LDSM_X4(A[1][0], A[1][1], A[1][2], A[1][3], a_addr1);

        // -- prefetch next iteration's feat (overlaps MMAs below) --
        {
            const int itn = (it + 64 < rows_per_cta) ? it + 64 : it;
            const float4* fpn = fbase + (size_t)itn * 8;
            #pragma unroll
            for (int q = 0; q < 4; q++)
                v[q] = fpn[(size_t)(ld_r0 + 4 * q) * 8 + ld_c4];
        }

        // -- layer 0: [16,32] @ W0 (B streamed from SMEM) --
        float c[8][4];
        #pragma unroll
        for (int nt = 0; nt < 8; nt++) {
            float2 bv = lds64(sb0 + (uint32_t)nt * 32);
            c[nt][0] = bv.x; c[nt][1] = bv.y;
            c[nt][2] = bv.x; c[nt][3] = bv.y;
        }
        #pragma unroll
        for (int kt = 0; kt < 2; kt++)
            #pragma unroll
            for (int np = 0; np < 8; np += 2) {
                uint32_t b0r, b1r, b2r, b3r;
                LDSM_X4(b0r, b1r, b2r, b3r,
                        w0b + bl4 + (uint32_t)np * (8 * WSTR * 2) + kt * 32);
                MMA16816(c[np],     A[kt][0], A[kt][1], A[kt][2], A[kt][3], b0r, b1r);
                MMA16816(c[np + 1], A[kt][0], A[kt][1], A[kt][2], A[kt][3], b2r, b3r);
            }

        // -- repack C -> A (relu fused, registers only) --
        #pragma unroll
        for (int kt = 0; kt < 4; kt++) {
            A[kt][0] = pack_relu2(c[2 * kt][0],     c[2 * kt][1]);
            A[kt][1] = pack_relu2(c[2 * kt][2],     c[2 * kt][3]);
            A[kt][2] = pack_relu2(c[2 * kt + 1][0], c[2 * kt + 1][1]);
            A[kt][3] = pack_relu2(c[2 * kt + 1][2], c[2 * kt + 1][3]);
        }

        // -- layer 1: [16,64] @ W1 --
        #pragma unroll
        for (int nt = 0; nt < 8; nt++) {
            float2 bv = lds64(sb1 + (uint32_t)nt * 32);
            c[nt][0] = bv.x; c[nt][1] = bv.y;
            c[nt][2] = bv.x; c[nt][3] = bv.y;
        }
        #pragma unroll
        for (int kt = 0; kt < 4; kt++)
            #pragma unroll
            for (int np = 0; np < 8; np += 2) {
                uint32_t b0r, b1r, b2r, b3r;
                LDSM_X4(b0r, b1r, b2r, b3r,
                        w1b + bl4 + (uint32_t)np * (8 * WSTR * 2) + kt * 32);
                MMA16816(c[np],     A[kt][0], A[kt][1], A[kt][2], A[kt][3], b0r, b1r);
                MMA16816(c[np + 1], A[kt][0], A[kt][1], A[kt][2], A[kt][3], b2r, b3r);
            }

        // -- repack again --
        #pragma unroll
        for (int kt = 0; kt < 4; kt++) {
            A[kt][0] = pack_relu2(c[2 * kt][0],     c[2 * kt][1]);
            A[kt][1] = pack_relu2(c[2 * kt][2],     c[2 * kt][3]);
            A[kt][2] = pack_relu2(c[2 * kt + 1][0], c[2 * kt + 1][1]);
            A[kt][3] = pack_relu2(c[2 * kt + 1][2], c[2 * kt + 1][3]);
        }

        // -- heads: [16,64] @ [Ws|Wr|0] -> [16,24] --
        float ch[3][4];
        #pragma unroll
        for (int nt = 0; nt < 3; nt++) {
            float2 bv = lds64(sbh + (uint32_t)nt * 32);
            ch[nt][0] = bv.x; ch[nt][1] = bv.y;
            ch[nt][2] = bv.x; ch[nt][3] = bv.y;
        }
        #pragma unroll
        for (int kt = 0; kt < 4; kt++) {
            uint32_t b0r, b1r, b2r, b3r;
            LDSM_X4(b0r, b1r, b2r, b3r, w2b + bl4 + kt * 32);
            MMA16816(ch[0], A[kt][0], A[kt][1], A[kt][2], A[kt][3], b0r, b1r);
            MMA16816(ch[1], A[kt][0], A[kt][1], A[kt][2], A[kt][3], b2r, b3r);
            uint32_t d0r, d1r;
            LDSM_X2(d0r, d1r, w2b + bl2 + (uint32_t)(16 * WSTR * 2) + kt * 32);
            MMA16816(ch[2], A[kt][0], A[kt][1], A[kt][2], A[kt][3], d0r, d1r);
        }

        // -- epilogue stores --
        const int gr0 = r0 + ep_row;
        const int gr1 = gr0 + 8;
        float* rg0 = rgb_out + (size_t)gr0 * 16;
        float* rg1 = rgb_out + (size_t)gr1 * 16;

        if (col2 == 0) {
            sigma_out[gr0] = softplus_dev(ch[0][0]);
            sigma_out[gr1] = softplus_dev(ch[0][2]);
            rg0[0]  = ch[0][1];  rg1[0]  = ch[0][3];
            rg0[15] = ch[2][0];  rg1[15] = ch[2][2];
        } else {
            rg0[col2 - 1] = ch[0][0];  rg0[col2] = ch[0][1];
            rg1[col2 - 1] = ch[0][2];  rg1[col2] = ch[0][3];
        }
        rg0[7 + col2] = ch[1][0];  rg0[8 + col2] = ch[1][1];
        rg1[7 + col2] = ch[1][2];  rg1[8 + col2] = ch[1][3];
    }
}

}  // namespace

extern "C" void kernel_launch(void* const* d_in, const int* in_sizes, int n_in,
                              void* d_out, int out_size) {
    const float* feat = (const float*)d_in[0];
    const float* W0   = (const float*)d_in[1];
    const float* b0   = (const float*)d_in[2];
    const float* W1   = (const float*)d_in[3];
    const float* b1   = (const float*)d_in[4];
    const float* Ws   = (const float*)d_in[5];
    const float* bs   = (const float*)d_in[6];
    const float* Wr   = (const float*)d_in[7];
    const float* br   = (const float*)d_in[8];

    float* out = (float*)d_out;
    const int Bn = in_sizes[0] / 32;           // rows (2^21)
    float* sigma = out;                         // [B]
    float* rgb   = out + Bn;                    // [B,16]

    const int rpc = Bn / NCTA;                  // 1024
    ngp_mlp_kernel<<<NCTA, CTA_THREADS>>>(feat, W0, b0, W1, b1, Ws, bs, Wr, br,
                                          sigma, rgb, rpc);
}

// round 7
// speedup vs baseline: 1.4163x; 1.0252x over previous
#include <cuda_runtime.h>
#include <cuda_fp16.h>
#include <cstdint>
#include <math.h>

// ---------------------------------------------------------------------------
// Portable tensor-core path: mma.sync + ldmatrix (no sm_103a-gated PTX).
// Round 7: M=32 per warp (two m16 tiles) so each streamed B-fragment feeds
// 2 MMAs (halves weight-LDSM per row), and feat is loaded DIRECTLY into
// A-fragment layout via float2 LDGs (no activation SMEM, no STS/ldmatrix-A).
// ---------------------------------------------------------------------------

#define LDSM_X4(r0, r1, r2, r3, addr) \
    asm volatile("ldmatrix.sync.aligned.m8n8.x4.shared.b16 {%0,%1,%2,%3}, [%4];" \
                 : "=r"(r0), "=r"(r1), "=r"(r2), "=r"(r3) : "r"(addr))

#define LDSM_X2(r0, r1, addr) \
    asm volatile("ldmatrix.sync.aligned.m8n8.x2.shared.b16 {%0,%1}, [%2];" \
                 : "=r"(r0), "=r"(r1) : "r"(addr))

#define MMA16816(c, a0, a1, a2, a3, b0, b1) \
    asm volatile("mma.sync.aligned.m16n8k16.row.col.f32.f16.f16.f32 " \
                 "{%0,%1,%2,%3}, {%4,%5,%6,%7}, {%8,%9}, {%0,%1,%2,%3};" \
                 : "+f"((c)[0]), "+f"((c)[1]), "+f"((c)[2]), "+f"((c)[3]) \
                 : "r"(a0), "r"(a1), "r"(a2), "r"(a3), "r"(b0), "r"(b1))

namespace {

__device__ __forceinline__ uint32_t smem_u32(const void* p) {
    uint32_t a;
    asm("{ .reg .u64 t; cvta.to.shared.u64 t, %1; cvt.u32.u64 %0, t; }"
        : "=r"(a) : "l"(p));
    return a;
}

__device__ __forceinline__ uint32_t pack_f16x2(float lo, float hi) {
    uint32_t r;
    asm("cvt.rn.f16x2.f32 %0, %1, %2;" : "=r"(r) : "f"(hi), "f"(lo));
    return r;
}

// pack two floats to f16x2 then relu both halves in one max.f16x2
__device__ __forceinline__ uint32_t pack_relu2(float lo, float hi) {
    uint32_t r = pack_f16x2(lo, hi);
    asm("max.f16x2 %0, %0, %1;" : "+r"(r) : "r"(0u));
    return r;
}

// non-hoistable bias load
__device__ __forceinline__ float2 lds64(uint32_t addr) {
    float2 r;
    asm volatile("ld.shared.v2.f32 {%0,%1}, [%2];"
                 : "=f"(r.x), "=f"(r.y) : "r"(addr));
    return r;
}

__device__ __forceinline__ float softplus_dev(float s) {
    return (s > 20.0f) ? s : log1pf(expf(s));
}

constexpr int WSTR = 72;     // halfs per SMEM row (144B) -> ldmatrix conflict-free
constexpr int NCTA = 2048;
constexpr int CTA_THREADS = 128;

__global__ void __launch_bounds__(128, 3) ngp_mlp_kernel(
    const float* __restrict__ feat,
    const float* __restrict__ W0, const float* __restrict__ b0,
    const float* __restrict__ W1, const float* __restrict__ b1,
    const float* __restrict__ Ws, const float* __restrict__ bs,
    const float* __restrict__ Wr, const float* __restrict__ br,
    float* __restrict__ sigma_out, float* __restrict__ rgb_out,
    int rows_per_cta)
{
    __shared__ __half w0t[64 * WSTR];      // [n<64][k<32] fp16, transposed
    __shared__ __half w1t[64 * WSTR];      // [n<64][k<64]
    __shared__ __half w2t[24 * WSTR];      // [n<24][k<64]; n0=Ws, n1..16=Wr
    __shared__ float  sbias[152];          // b0 | b1 | head(bs-1, br, 0)

    const int tid  = threadIdx.x;
    const int wid  = tid >> 5;
    const int lane = tid & 31;

    // ---- stage weights: fp32 gmem [K][N] -> fp16 smem [N][K] ----
    for (int i = tid; i < 32 * 64; i += CTA_THREADS) {
        int k = i >> 6, n = i & 63;
        w0t[n * WSTR + k] = __float2half(W0[i]);
    }
    for (int i = tid; i < 64 * 64; i += CTA_THREADS) {
        int k = i >> 6, n = i & 63;
        w1t[n * WSTR + k] = __float2half(W1[i]);
    }
    for (int i = tid; i < 24 * WSTR; i += CTA_THREADS)
        w2t[i] = __float2half(0.0f);
    if (tid < 64) { sbias[tid] = b0[tid]; sbias[64 + tid] = b1[tid]; }
    if (tid < 24)
        sbias[128 + tid] = (tid == 0) ? (bs[0] - 1.0f)
                         : (tid <= 16 ? br[tid - 1] : 0.0f);
    __syncthreads();
    if (tid < 64)
        w2t[0 * WSTR + tid] = __float2half(Ws[tid]);        // col 0: sigma
    for (int i = tid; i < 64 * 16; i += CTA_THREADS) {       // cols 1..16: rgb
        int k = i >> 4, n = i & 15;
        w2t[(n + 1) * WSTR + k] = __float2half(Wr[i]);
    }
    __syncthreads();

    // ---- addressing ----
    const uint32_t w0b = smem_u32(w0t), w1b = smem_u32(w1t), w2b = smem_u32(w2t);
    const uint32_t sb  = smem_u32(sbias);
    const int l15  = lane & 15;
    const int col2 = (lane & 3) * 2;

    // B-fragment ldmatrix lane terms
    const uint32_t bl4 = (uint32_t)((((lane >> 4) & 1) * 8 + (lane & 7)) * (WSTR * 2)
                                    + ((lane >> 3) & 1) * 16);
    const uint32_t bl2 = (uint32_t)((l15 & 7) * (WSTR * 2) + ((l15 >> 3) & 1) * 16);

    const int ep_row   = lane >> 2;          // also A-fragment row within tile
    const int cq       = lane & 3;           // float2-column quad index

    const uint32_t sb0 = sb + (uint32_t)col2 * 4;        // b0
    const uint32_t sb1 = sb0 + 256;                      // b1
    const uint32_t sbh = sb0 + 512;                      // head

    const int cta_base = blockIdx.x * rows_per_cta;
    const float2* f2 = (const float2*)feat;

    // prime pipeline: feat for iter 0, directly in fragment layout
    // vf[t][h][o]: tile t (rows +16t), row-half h (rows +8h), k-offset o (cols 2c+8o)
    float2 vf[2][2][4];
    {
        size_t base = (size_t)(cta_base + wid * 32 + ep_row) * 16 + cq;
        #pragma unroll
        for (int t = 0; t < 2; t++)
            #pragma unroll
            for (int h = 0; h < 2; h++)
                #pragma unroll
                for (int o = 0; o < 4; o++)
                    vf[t][h][o] = f2[base + (size_t)(t * 16 + h * 8) * 16 + o * 4];
    }

    #pragma unroll 1
    for (int it = 0; it < rows_per_cta; it += 128) {
        const int warp_r0 = cta_base + it + wid * 32;

        // -- convert prefetched feat to layer-0 A fragments (registers only) --
        uint32_t A0[2][2][4];   // [tile][kt][reg]
        #pragma unroll
        for (int t = 0; t < 2; t++)
            #pragma unroll
            for (int o = 0; o < 4; o++)
                #pragma unroll
                for (int h = 0; h < 2; h++)
                    A0[t][o >> 1][(o & 1) * 2 + h] =
                        pack_f16x2(vf[t][h][o].x, vf[t][h][o].y);

        // -- prefetch next iteration's feat (overlaps all MMAs below) --
        {
            const int itn = (it + 128 < rows_per_cta) ? it + 128 : it;
            size_t base = (size_t)(cta_base + itn + wid * 32 + ep_row) * 16 + cq;
            #pragma unroll
            for (int t = 0; t < 2; t++)
                #pragma unroll
                for (int h = 0; h < 2; h++)
                    #pragma unroll
                    for (int o = 0; o < 4; o++)
                        vf[t][h][o] = f2[base + (size_t)(t * 16 + h * 8) * 16 + o * 4];
        }

        // -- layer 0: [32,32] @ W0; each B-fragment feeds both tiles --
        float c[2][8][4];
        #pragma unroll
        for (int nt = 0; nt < 8; nt++) {
            float2 bv = lds64(sb0 + (uint32_t)nt * 32);
            #pragma unroll
            for (int t = 0; t < 2; t++) {
                c[t][nt][0] = bv.x; c[t][nt][1] = bv.y;
                c[t][nt][2] = bv.x; c[t][nt][3] = bv.y;
            }
        }
        #pragma unroll
        for (int kt = 0; kt < 2; kt++)
            #pragma unroll
            for (int np = 0; np < 8; np += 2) {
                uint32_t b0r, b1r, b2r, b3r;
                LDSM_X4(b0r, b1r, b2r, b3r,
                        w0b + bl4 + (uint32_t)np * (8 * WSTR * 2) + kt * 32);
                #pragma unroll
                for (int t = 0; t < 2; t++) {
                    MMA16816(c[t][np],     A0[t][kt][0], A0[t][kt][1],
                             A0[t][kt][2], A0[t][kt][3], b0r, b1r);
                    MMA16816(c[t][np + 1], A0[t][kt][0], A0[t][kt][1],
                             A0[t][kt][2], A0[t][kt][3], b2r, b3r);
                }
            }

        // -- repack C -> A (relu fused, registers only) --
        uint32_t A1[2][4][4];
        #pragma unroll
        for (int t = 0; t < 2; t++)
            #pragma unroll
            for (int kt = 0; kt < 4; kt++) {
                A1[t][kt][0] = pack_relu2(c[t][2 * kt][0],     c[t][2 * kt][1]);
                A1[t][kt][1] = pack_relu2(c[t][2 * kt][2],     c[t][2 * kt][3]);
                A1[t][kt][2] = pack_relu2(c[t][2 * kt + 1][0], c[t][2 * kt + 1][1]);
                A1[t][kt][3] = pack_relu2(c[t][2 * kt + 1][2], c[t][2 * kt + 1][3]);
            }

        // -- layer 1: [32,64] @ W1 --
        #pragma unroll
        for (int nt = 0; nt < 8; nt++) {
            float2 bv = lds64(sb1 + (uint32_t)nt * 32);
            #pragma unroll
            for (int t = 0; t < 2; t++) {
                c[t][nt][0] = bv.x; c[t][nt][1] = bv.y;
                c[t][nt][2] = bv.x; c[t][nt][3] = bv.y;
            }
        }
        #pragma unroll
        for (int kt = 0; kt < 4; kt++)
            #pragma unroll
            for (int np = 0; np < 8; np += 2) {
                uint32_t b0r, b1r, b2r, b3r;
                LDSM_X4(b0r, b1r, b2r, b3r,
                        w1b + bl4 + (uint32_t)np * (8 * WSTR * 2) + kt * 32);
                #pragma unroll
                for (int t = 0; t < 2; t++) {
                    MMA16816(c[t][np],     A1[t][kt][0], A1[t][kt][1],
                             A1[t][kt][2], A1[t][kt][3], b0r, b1r);
                    MMA16816(c[t][np + 1], A1[t][kt][0], A1[t][kt][1],
                             A1[t][kt][2], A1[t][kt][3], b2r, b3r);
                }
            }

        // -- repack again (reuse A1 storage) --
        #pragma unroll
        for (int t = 0; t < 2; t++)
            #pragma unroll
            for (int kt = 0; kt < 4; kt++) {
                A1[t][kt][0] = pack_relu2(c[t][2 * kt][0],     c[t][2 * kt][1]);
                A1[t][kt][1] = pack_relu2(c[t][2 * kt][2],     c[t][2 * kt][3]);
                A1[t][kt][2] = pack_relu2(c[t][2 * kt + 1][0], c[t][2 * kt + 1][1]);
                A1[t][kt][3] = pack_relu2(c[t][2 * kt + 1][2], c[t][2 * kt + 1][3]);
            }

        // -- heads: [32,64] @ [Ws|Wr|0] -> [32,24] --
        float ch[2][3][4];
        #pragma unroll
        for (int nt = 0; nt < 3; nt++) {
            float2 bv = lds64(sbh + (uint32_t)nt * 32);
            #pragma unroll
            for (int t = 0; t < 2; t++) {
                ch[t][nt][0] = bv.x; ch[t][nt][1] = bv.y;
                ch[t][nt][2] = bv.x; ch[t][nt][3] = bv.y;
            }
        }
        #pragma unroll
        for (int kt = 0; kt < 4; kt++) {
            uint32_t b0r, b1r, b2r, b3r;
            LDSM_X4(b0r, b1r, b2r, b3r, w2b + bl4 + kt * 32);
            uint32_t d0r, d1r;
            LDSM_X2(d0r, d1r, w2b + bl2 + (uint32_t)(16 * WSTR * 2) + kt * 32);
            #pragma unroll
            for (int t = 0; t < 2; t++) {
                MMA16816(ch[t][0], A1[t][kt][0], A1[t][kt][1],
                         A1[t][kt][2], A1[t][kt][3], b0r, b1r);
                MMA16816(ch[t][1], A1[t][kt][0], A1[t][kt][1],
                         A1[t][kt][2], A1[t][kt][3], b2r, b3r);
                MMA16816(ch[t][2], A1[t][kt][0], A1[t][kt][1],
                         A1[t][kt][2], A1[t][kt][3], d0r, d1r);
            }
        }

        // -- epilogue stores (per tile) --
        #pragma unroll
        for (int t = 0; t < 2; t++) {
            const int gr0 = warp_r0 + t * 16 + ep_row;
            const int gr1 = gr0 + 8;
            float* rg0 = rgb_out + (size_t)gr0 * 16;
            float* rg1 = rgb_out + (size_t)gr1 * 16;

            if (col2 == 0) {
                sigma_out[gr0] = softplus_dev(ch[t][0][0]);
                sigma_out[gr1] = softplus_dev(ch[t][0][2]);
                rg0[0]  = ch[t][0][1];  rg1[0]  = ch[t][0][3];
                rg0[15] = ch[t][2][0];  rg1[15] = ch[t][2][2];
            } else {
                rg0[col2 - 1] = ch[t][0][0];  rg0[col2] = ch[t][0][1];
                rg1[col2 - 1] = ch[t][0][2];  rg1[col2] = ch[t][0][3];
            }
            rg0[7 + col2] = ch[t][1][0];  rg0[8 + col2] = ch[t][1][1];
            rg1[7 + col2] = ch[t][1][2];  rg1[8 + col2] = ch[t][1][3];
        }
    }
}

}  // namespace

extern "C" void kernel_launch(void* const* d_in, const int* in_sizes, int n_in,
                              void* d_out, int out_size) {
    const float* feat = (const float*)d_in[0];
    const float* W0   = (const float*)d_in[1];
    const float* b0   = (const float*)d_in[2];
    const float* W1   = (const float*)d_in[3];
    const float* b1   = (const float*)d_in[4];
    const float* Ws   = (const float*)d_in[5];
    const float* bs   = (const float*)d_in[6];
    const float* Wr   = (const float*)d_in[7];
    const float* br   = (const float*)d_in[8];

    float* out = (float*)d_out;
    const int Bn = in_sizes[0] / 32;           // rows (2^21)
    float* sigma = out;                         // [B]
    float* rgb   = out + Bn;                    // [B,16]

    const int rpc = Bn / NCTA;                  // 1024
    ngp_mlp_kernel<<<NCTA, CTA_THREADS>>>(feat, W0, b0, W1, b1, Ws, bs, Wr, br,
                                          sigma, rgb, rpc);
}

// round 8
// speedup vs baseline: 1.4969x; 1.0569x over previous
#include <cuda_runtime.h>
#include <cuda_fp16.h>
#include <cstdint>
#include <math.h>

// ---------------------------------------------------------------------------
// Portable tensor-core path: mma.sync + ldmatrix (no sm_103a-gated PTX).
// Round 8: M=32 per warp (two m16 tiles, B-fragments amortized), feat loaded
// directly into A-fragment layout. Prefetch moved AFTER layer-1 so the 32-reg
// prefetch buffer is not live across the register peak -> 4 CTAs/SM.
// ---------------------------------------------------------------------------

#define LDSM_X4(r0, r1, r2, r3, addr) \
    asm volatile("ldmatrix.sync.aligned.m8n8.x4.shared.b16 {%0,%1,%2,%3}, [%4];" \
                 : "=r"(r0), "=r"(r1), "=r"(r2), "=r"(r3) : "r"(addr))

#define LDSM_X2(r0, r1, addr) \
    asm volatile("ldmatrix.sync.aligned.m8n8.x2.shared.b16 {%0,%1}, [%2];" \
                 : "=r"(r0), "=r"(r1) : "r"(addr))

#define MMA16816(c, a0, a1, a2, a3, b0, b1) \
    asm volatile("mma.sync.aligned.m16n8k16.row.col.f32.f16.f16.f32 " \
                 "{%0,%1,%2,%3}, {%4,%5,%6,%7}, {%8,%9}, {%0,%1,%2,%3};" \
                 : "+f"((c)[0]), "+f"((c)[1]), "+f"((c)[2]), "+f"((c)[3]) \
                 : "r"(a0), "r"(a1), "r"(a2), "r"(a3), "r"(b0), "r"(b1))

namespace {

__device__ __forceinline__ uint32_t smem_u32(const void* p) {
    uint32_t a;
    asm("{ .reg .u64 t; cvta.to.shared.u64 t, %1; cvt.u32.u64 %0, t; }"
        : "=r"(a) : "l"(p));
    return a;
}

__device__ __forceinline__ uint32_t pack_f16x2(float lo, float hi) {
    uint32_t r;
    asm("cvt.rn.f16x2.f32 %0, %1, %2;" : "=r"(r) : "f"(hi), "f"(lo));
    return r;
}

// pack two floats to f16x2 then relu both halves in one max.f16x2
__device__ __forceinline__ uint32_t pack_relu2(float lo, float hi) {
    uint32_t r = pack_f16x2(lo, hi);
    asm("max.f16x2 %0, %0, %1;" : "+r"(r) : "r"(0u));
    return r;
}

// non-hoistable bias load
__device__ __forceinline__ float2 lds64(uint32_t addr) {
    float2 r;
    asm volatile("ld.shared.v2.f32 {%0,%1}, [%2];"
                 : "=f"(r.x), "=f"(r.y) : "r"(addr));
    return r;
}

__device__ __forceinline__ float softplus_dev(float s) {
    return (s > 20.0f) ? s : log1pf(expf(s));
}

constexpr int WSTR = 72;     // halfs per SMEM row (144B) -> ldmatrix conflict-free
constexpr int NCTA = 2048;
constexpr int CTA_THREADS = 128;

__global__ void __launch_bounds__(128, 4) ngp_mlp_kernel(
    const float* __restrict__ feat,
    const float* __restrict__ W0, const float* __restrict__ b0,
    const float* __restrict__ W1, const float* __restrict__ b1,
    const float* __restrict__ Ws, const float* __restrict__ bs,
    const float* __restrict__ Wr, const float* __restrict__ br,
    float* __restrict__ sigma_out, float* __restrict__ rgb_out,
    int rows_per_cta)
{
    __shared__ __half w0t[64 * WSTR];      // [n<64][k<32] fp16, transposed
    __shared__ __half w1t[64 * WSTR];      // [n<64][k<64]
    __shared__ __half w2t[24 * WSTR];      // [n<24][k<64]; n0=Ws, n1..16=Wr
    __shared__ float  sbias[152];          // b0 | b1 | head(bs-1, br, 0)

    const int tid  = threadIdx.x;
    const int wid  = tid >> 5;
    const int lane = tid & 31;

    // ---- stage weights: fp32 gmem [K][N] -> fp16 smem [N][K] ----
    for (int i = tid; i < 32 * 64; i += CTA_THREADS) {
        int k = i >> 6, n = i & 63;
        w0t[n * WSTR + k] = __float2half(W0[i]);
    }
    for (int i = tid; i < 64 * 64; i += CTA_THREADS) {
        int k = i >> 6, n = i & 63;
        w1t[n * WSTR + k] = __float2half(W1[i]);
    }
    for (int i = tid; i < 24 * WSTR; i += CTA_THREADS)
        w2t[i] = __float2half(0.0f);
    if (tid < 64) { sbias[tid] = b0[tid]; sbias[64 + tid] = b1[tid]; }
    if (tid < 24)
        sbias[128 + tid] = (tid == 0) ? (bs[0] - 1.0f)
                         : (tid <= 16 ? br[tid - 1] : 0.0f);
    __syncthreads();
    if (tid < 64)
        w2t[0 * WSTR + tid] = __float2half(Ws[tid]);        // col 0: sigma
    for (int i = tid; i < 64 * 16; i += CTA_THREADS) {       // cols 1..16: rgb
        int k = i >> 4, n = i & 15;
        w2t[(n + 1) * WSTR + k] = __float2half(Wr[i]);
    }
    __syncthreads();

    // ---- addressing ----
    const uint32_t w0b = smem_u32(w0t), w1b = smem_u32(w1t), w2b = smem_u32(w2t);
    const uint32_t sb  = smem_u32(sbias);
    const int l15  = lane & 15;
    const int col2 = (lane & 3) * 2;

    // B-fragment ldmatrix lane terms
    const uint32_t bl4 = (uint32_t)((((lane >> 4) & 1) * 8 + (lane & 7)) * (WSTR * 2)
                                    + ((lane >> 3) & 1) * 16);
    const uint32_t bl2 = (uint32_t)((l15 & 7) * (WSTR * 2) + ((l15 >> 3) & 1) * 16);

    const int ep_row   = lane >> 2;          // A-fragment row within tile
    const int cq       = lane & 3;           // float2-column quad index

    const uint32_t sb0 = sb + (uint32_t)col2 * 4;        // b0
    const uint32_t sb1 = sb0 + 256;                      // b1
    const uint32_t sbh = sb0 + 512;                      // head

    const int cta_base = blockIdx.x * rows_per_cta;
    const float2* f2 = (const float2*)feat;

    // prime pipeline: feat for iter 0 in fragment layout
    // vf[t][h][o]: tile t (rows +16t), row-half h (rows +8h), k-offset o
    float2 vf[2][2][4];
    {
        size_t base = (size_t)(cta_base + wid * 32 + ep_row) * 16 + cq;
        #pragma unroll
        for (int t = 0; t < 2; t++)
            #pragma unroll
            for (int h = 0; h < 2; h++)
                #pragma unroll
                for (int o = 0; o < 4; o++)
                    vf[t][h][o] = f2[base + (size_t)(t * 16 + h * 8) * 16 + o * 4];
    }

    #pragma unroll 1
    for (int it = 0; it < rows_per_cta; it += 128) {
        const int warp_r0 = cta_base + it + wid * 32;

        // -- convert prefetched feat to layer-0 A fragments (vf dies here) --
        uint32_t A0[2][2][4];   // [tile][kt][reg]
        #pragma unroll
        for (int t = 0; t < 2; t++)
            #pragma unroll
            for (int o = 0; o < 4; o++)
                #pragma unroll
                for (int h = 0; h < 2; h++)
                    A0[t][o >> 1][(o & 1) * 2 + h] =
                        pack_f16x2(vf[t][h][o].x, vf[t][h][o].y);

        // -- layer 0: [32,32] @ W0; each B-fragment feeds both tiles --
        float c[2][8][4];
        #pragma unroll
        for (int nt = 0; nt < 8; nt++) {
            float2 bv = lds64(sb0 + (uint32_t)nt * 32);
            #pragma unroll
            for (int t = 0; t < 2; t++) {
                c[t][nt][0] = bv.x; c[t][nt][1] = bv.y;
                c[t][nt][2] = bv.x; c[t][nt][3] = bv.y;
            }
        }
        #pragma unroll
        for (int kt = 0; kt < 2; kt++)
            #pragma unroll
            for (int np = 0; np < 8; np += 2) {
                uint32_t b0r, b1r, b2r, b3r;
                LDSM_X4(b0r, b1r, b2r, b3r,
                        w0b + bl4 + (uint32_t)np * (8 * WSTR * 2) + kt * 32);
                #pragma unroll
                for (int t = 0; t < 2; t++) {
                    MMA16816(c[t][np],     A0[t][kt][0], A0[t][kt][1],
                             A0[t][kt][2], A0[t][kt][3], b0r, b1r);
                    MMA16816(c[t][np + 1], A0[t][kt][0], A0[t][kt][1],
                             A0[t][kt][2], A0[t][kt][3], b2r, b3r);
                }
            }

        // -- repack C -> A (relu fused, registers only) --
        uint32_t A1[2][4][4];
        #pragma unroll
        for (int t = 0; t < 2; t++)
            #pragma unroll
            for (int kt = 0; kt < 4; kt++) {
                A1[t][kt][0] = pack_relu2(c[t][2 * kt][0],     c[t][2 * kt][1]);
                A1[t][kt][1] = pack_relu2(c[t][2 * kt][2],     c[t][2 * kt][3]);
                A1[t][kt][2] = pack_relu2(c[t][2 * kt + 1][0], c[t][2 * kt + 1][1]);
                A1[t][kt][3] = pack_relu2(c[t][2 * kt + 1][2], c[t][2 * kt + 1][3]);
            }

        // -- layer 1: [32,64] @ W1 --
        #pragma unroll
        for (int nt = 0; nt < 8; nt++) {
            float2 bv = lds64(sb1 + (uint32_t)nt * 32);
            #pragma unroll
            for (int t = 0; t < 2; t++) {
                c[t][nt][0] = bv.x; c[t][nt][1] = bv.y;
                c[t][nt][2] = bv.x; c[t][nt][3] = bv.y;
            }
        }
        #pragma unroll
        for (int kt = 0; kt < 4; kt++)
            #pragma unroll
            for (int np = 0; np < 8; np += 2) {
                uint32_t b0r, b1r, b2r, b3r;
                LDSM_X4(b0r, b1r, b2r, b3r,
                        w1b + bl4 + (uint32_t)np * (8 * WSTR * 2) + kt * 32);
                #pragma unroll
                for (int t = 0; t < 2; t++) {
                    MMA16816(c[t][np],     A1[t][kt][0], A1[t][kt][1],
                             A1[t][kt][2], A1[t][kt][3], b0r, b1r);
                    MMA16816(c[t][np + 1], A1[t][kt][0], A1[t][kt][1],
                             A1[t][kt][2], A1[t][kt][3], b2r, b3r);
                }
            }

        // -- LATE prefetch of next iteration's feat --
        // vf becomes live only from here to loop top; it is NOT live across
        // the layer-1 register peak above, freeing ~32 regs for occupancy.
        {
            const int itn = (it + 128 < rows_per_cta) ? it + 128 : it;
            size_t base = (size_t)(cta_base + itn + wid * 32 + ep_row) * 16 + cq;
            #pragma unroll
            for (int t = 0; t < 2; t++)
                #pragma unroll
                for (int h = 0; h < 2; h++)
                    #pragma unroll
                    for (int o = 0; o < 4; o++)
                        vf[t][h][o] = f2[base + (size_t)(t * 16 + h * 8) * 16 + o * 4];
        }

        // -- repack again (reuse A1 storage) --
        #pragma unroll
        for (int t = 0; t < 2; t++)
            #pragma unroll
            for (int kt = 0; kt < 4; kt++) {
                A1[t][kt][0] = pack_relu2(c[t][2 * kt][0],     c[t][2 * kt][1]);
                A1[t][kt][1] = pack_relu2(c[t][2 * kt][2],     c[t][2 * kt][3]);
                A1[t][kt][2] = pack_relu2(c[t][2 * kt + 1][0], c[t][2 * kt + 1][1]);
                A1[t][kt][3] = pack_relu2(c[t][2 * kt + 1][2], c[t][2 * kt + 1][3]);
            }

        // -- heads: [32,64] @ [Ws|Wr|0] -> [32,24] --
        float ch[2][3][4];
        #pragma unroll
        for (int nt = 0; nt < 3; nt++) {
            float2 bv = lds64(sbh + (uint32_t)nt * 32);
            #pragma unroll
            for (int t = 0; t < 2; t++) {
                ch[t][nt][0] = bv.x; ch[t][nt][1] = bv.y;
                ch[t][nt][2] = bv.x; ch[t][nt][3] = bv.y;
            }
        }
        #pragma unroll
        for (int kt = 0; kt < 4; kt++) {
            uint32_t b0r, b1r, b2r, b3r;
            LDSM_X4(b0r, b1r, b2r, b3r, w2b + bl4 + kt * 32);
            uint32_t d0r, d1r;
            LDSM_X2(d0r, d1r, w2b + bl2 + (uint32_t)(16 * WSTR * 2) + kt * 32);
            #pragma unroll
            for (int t = 0; t < 2; t++) {
                MMA16816(ch[t][0], A1[t][kt][0], A1[t][kt][1],
                         A1[t][kt][2], A1[t][kt][3], b0r, b1r);
                MMA16816(ch[t][1], A1[t][kt][0], A1[t][kt][1],
                         A1[t][kt][2], A1[t][kt][3], b2r, b3r);
                MMA16816(ch[t][2], A1[t][kt][0], A1[t][kt][1],
                         A1[t][kt][2], A1[t][kt][3], d0r, d1r);
            }
        }

        // -- epilogue stores (per tile) --
        #pragma unroll
        for (int t = 0; t < 2; t++) {
            const int gr0 = warp_r0 + t * 16 + ep_row;
            const int gr1 = gr0 + 8;
            float* rg0 = rgb_out + (size_t)gr0 * 16;
            float* rg1 = rgb_out + (size_t)gr1 * 16;

            if (col2 == 0) {
                sigma_out[gr0] = softplus_dev(ch[t][0][0]);
                sigma_out[gr1] = softplus_dev(ch[t][0][2]);
                rg0[0]  = ch[t][0][1];  rg1[0]  = ch[t][0][3];
                rg0[15] = ch[t][2][0];  rg1[15] = ch[t][2][2];
            } else {
                rg0[col2 - 1] = ch[t][0][0];  rg0[col2] = ch[t][0][1];
                rg1[col2 - 1] = ch[t][0][2];  rg1[col2] = ch[t][0][3];
            }
            rg0[7 + col2] = ch[t][1][0];  rg0[8 + col2] = ch[t][1][1];
            rg1[7 + col2] = ch[t][1][2];  rg1[8 + col2] = ch[t][1][3];
        }
    }
}

}  // namespace

extern "C" void kernel_launch(void* const* d_in, const int* in_sizes, int n_in,
                              void* d_out, int out_size) {
    const float* feat = (const float*)d_in[0];
    const float* W0   = (const float*)d_in[1];
    const float* b0   = (const float*)d_in[2];
    const float* W1   = (const float*)d_in[3];
    const float* b1   = (const float*)d_in[4];
    const float* Ws   = (const float*)d_in[5];
    const float* bs   = (const float*)d_in[6];
    const float* Wr   = (const float*)d_in[7];
    const float* br   = (const float*)d_in[8];

    float* out = (float*)d_out;
    const int Bn = in_sizes[0] / 32;           // rows (2^21)
    float* sigma = out;                         // [B]
    float* rgb   = out + Bn;                    // [B,16]

    const int rpc = Bn / NCTA;                  // 1024
    ngp_mlp_kernel<<<NCTA, CTA_THREADS>>>(feat, W0, b0, W1, b1, Ws, bs, Wr, br,
                                          sigma, rgb, rpc);
}